// round 8
// baseline (speedup 1.0000x reference)
#include <cuda_runtime.h>
#include <math.h>

#define Bsz 256
#define Tt  500
#define Ii  128
#define Hh  512
#define CLIPV 5.0f

#define NBLK 128
#define NTHR 512
#define MT   16          // out columns per block (x3 gates)
#define BT   64          // batches per block
#define NSPL 4           // K-splits (160 k each, 20 k8-steps)
#define KPS  160
#define KCH  16          // staged k per chunk
#define NCH  10          // chunks per split
#define ASTR 66          // padded batch stride in staged tile (float2 units)
#define AST_BUF (KCH * ASTR)                       // float2 per buffer
#define SPL_SMEM (2 * AST_BUF * 8)                 // 16896 B per split
#define SMEM_BYTES (NSPL * SPL_SMEM)               // 67584 B

typedef unsigned long long ull;

__device__ float    g_h[2][Bsz * Hh];
__device__ float4   g_wp[3 * 64 * 80 * 32];        // [gate][m8][kstep][lane]
__device__ unsigned g_cnt   = 0;
__device__ unsigned g_phase = 0;

__device__ __forceinline__ float tf32r(float v) {
    unsigned r;
    asm("cvt.rna.tf32.f32 %0, %1;" : "=r"(r) : "f"(v));
    return __uint_as_float(r);
}
__device__ __forceinline__ float sigf(float x) { return 1.f / (1.f + __expf(-x)); }

#define MMA_TF32(D, A0, A1, A2, A3, B0, B1)                              \
    asm volatile("mma.sync.aligned.m16n8k8.row.col.f32.tf32.tf32.f32 "   \
                 "{%0,%1,%2,%3},{%4,%5,%6,%7},{%8,%9},{%0,%1,%2,%3};"    \
                 : "+f"(D[0]), "+f"(D[1]), "+f"(D[2]), "+f"(D[3])        \
                 : "r"(A0), "r"(A1), "r"(A2), "r"(A3), "r"(B0), "r"(B1))

// One-time: split weights to tf32 hi/lo, packed in per-lane fragment order.
__global__ void pack_w(const float* __restrict__ w_ih, const float* __restrict__ w_hh) {
    int idx = blockIdx.x * blockDim.x + threadIdx.x;
    if (idx >= 3 * 64 * 80 * 32) return;
    int lane  = idx & 31;
    int kstep = (idx >> 5) % 80;
    int m8    = ((idx >> 5) / 80) % 64;
    int g     = (idx >> 5) / (80 * 64);
    int n = g * Hh + m8 * 8 + (lane >> 2);
    int k = kstep * 8 + (lane & 3);
    float v0, v1;
    if (k < Hh) { v0 = w_hh[n * Hh + k];      v1 = w_hh[n * Hh + k + 4]; }
    else        { v0 = w_ih[n * Ii + k - Hh]; v1 = w_ih[n * Ii + k - Hh + 4]; }
    float h0 = tf32r(v0), h1 = tf32r(v1);
    g_wp[idx] = make_float4(h0, tf32r(v0 - h0), h1, tf32r(v1 - h1));
}

// Persistent GRU. 128 blocks (32 m-tiles x 4 batch-tiles), 512 threads.
// 16 warps = 2 batch-groups x 2 out-halves x 4 K-splits (4 warps/SMSP).
// Warp tile: 32 batch (2 M-frags) x 24 out (3 gates x n8) x 160 K (20 k8-steps).
__global__ void __launch_bounds__(NTHR, 1) gru_persist(
    const float* __restrict__ x,      // (B, T, I)
    const float* __restrict__ h0,     // (B, H)
    const float* __restrict__ b_ih,   // (3H)
    const float* __restrict__ b_hh,   // (3H)
    float* __restrict__ out)          // (B, T, H) then (B, H) tail
{
    extern __shared__ char sm[];

    const int tid  = threadIdx.x;
    const int lane = tid & 31;
    const int w    = tid >> 5;
    const int bg   = w & 1;            // batch group (32 each)
    const int hf   = (w >> 1) & 1;     // out half (8 m each)
    const int ks   = w >> 2;           // K-split (0..3, 160 k each)

    const int bm = blockIdx.x & 31;
    const int bt = blockIdx.x >> 5;
    const int m0 = bm * MT;
    const int b0 = bt * BT;
    const int m8blk = bm * 2 + hf;
    const int mcol  = m0 + hf * 8 + 2 * (lane & 3);

    // staged A (h/x) for this split: [buf][klocal][batch] float2{hi,lo}
    float2* Asplit = (float2*)(sm + ks * SPL_SMEM);
    const int colA = bg * 32 + (lane >> 2);

    // B fragment pointers (per gate)
    const float4* bp0 = g_wp + (((0 * 64 + m8blk) * 80 + ks * 20) * 32) + lane;
    const float4* bp1 = g_wp + (((1 * 64 + m8blk) * 80 + ks * 20) * 32) + lane;
    const float4* bp2 = g_wp + (((2 * 64 + m8blk) * 80 + ks * 20) * 32) + lane;

    unsigned bar_base = 0;
    if (tid == 0)
        asm volatile("ld.global.cg.u32 %0, [%1];" : "=r"(bar_base) : "l"(&g_phase));

    const float2 cR  = make_float2(b_ih[mcol] + b_hh[mcol],
                                   b_ih[mcol + 1] + b_hh[mcol + 1]);
    const float2 cZ  = make_float2(b_ih[Hh + mcol] + b_hh[Hh + mcol],
                                   b_ih[Hh + mcol + 1] + b_hh[Hh + mcol + 1]);
    const float2 cNx = make_float2(b_ih[2 * Hh + mcol], b_ih[2 * Hh + mcol + 1]);
    const float2 cNh = make_float2(b_hh[2 * Hh + mcol], b_hh[2 * Hh + mcol + 1]);

    // staging mapping: 128 threads per split stage 64 batch x 16 k
    const int th = tid & 127;
    const int bA = th & 63;            // batch row
    const int kh = (th >> 6) * 8;      // k sub-range (0 or 8)

    float4 st_regs[2];

    for (int t = 0; t < Tt; t++) {
        const float* hsrc = (t == 0) ? h0 : g_h[t & 1];
        float*       hdst = g_h[(t + 1) & 1];

        __align__(16) float aR[2][4], aZ[2][4], aN[2][4], aNx[2][4];
        #pragma unroll
        for (int mf = 0; mf < 2; mf++)
            #pragma unroll
            for (int i = 0; i < 4; i++)
                { aR[mf][i] = 0.f; aZ[mf][i] = 0.f; aN[mf][i] = 0.f; aNx[mf][i] = 0.f; }

        auto ldgA = [&](int c) {
            const int kc = ks * KPS + c * KCH;
            const float* p = (kc < Hh)
                ? hsrc + (size_t)(b0 + bA) * Hh + kc + kh
                : x + ((size_t)(b0 + bA) * Tt + t) * Ii + (kc - Hh) + kh;
            st_regs[0] = __ldcg((const float4*)p);
            st_regs[1] = __ldcg((const float4*)(p + 4));
        };
        auto stsA = [&](int buf) {
            float2* A = Asplit + buf * AST_BUF;
            #pragma unroll
            for (int j = 0; j < 2; j++) {
                const float vv[4] = {st_regs[j].x, st_regs[j].y, st_regs[j].z, st_regs[j].w};
                #pragma unroll
                for (int i = 0; i < 4; i++) {
                    const int kl = kh + 4 * j + i;
                    float hi = tf32r(vv[i]);
                    A[kl * ASTR + bA] = make_float2(hi, tf32r(vv[i] - hi));
                }
            }
        };

        float4 bb[3][3];               // B prefetch ring: [slot][gate]
        auto ldB = [&](int jq, int slot) {
            bb[slot][0] = bp0[jq * 32];
            bb[slot][1] = bp1[jq * 32];
            bb[slot][2] = bp2[jq * 32];
        };

        auto do_kstep = [&](int jj, const float2* Abuf, const float4* B, bool isH) {
            const int kb = jj * 8 + (lane & 3);
            const float2* r0 = Abuf + kb * ASTR + colA;
            const float2* r4 = Abuf + (kb + 4) * ASTR + colA;
            const unsigned bh[3][2] = {
                {__float_as_uint(B[0].x), __float_as_uint(B[0].z)},
                {__float_as_uint(B[1].x), __float_as_uint(B[1].z)},
                {__float_as_uint(B[2].x), __float_as_uint(B[2].z)}};
            const unsigned bl[3][2] = {
                {__float_as_uint(B[0].y), __float_as_uint(B[0].w)},
                {__float_as_uint(B[1].y), __float_as_uint(B[1].w)},
                {__float_as_uint(B[2].y), __float_as_uint(B[2].w)}};
            #pragma unroll
            for (int mf = 0; mf < 2; mf++) {
                float2 f0 = r0[mf * 16], f1 = r0[mf * 16 + 8];
                float2 f2 = r4[mf * 16], f3 = r4[mf * 16 + 8];
                unsigned ah0 = __float_as_uint(f0.x), ah1 = __float_as_uint(f1.x);
                unsigned ah2 = __float_as_uint(f2.x), ah3 = __float_as_uint(f3.x);
                unsigned al0 = __float_as_uint(f0.y), al1 = __float_as_uint(f1.y);
                unsigned al2 = __float_as_uint(f2.y), al3 = __float_as_uint(f3.y);
                float* aNs = isH ? aN[mf] : aNx[mf];
                MMA_TF32(aR[mf], ah0, ah1, ah2, ah3, bh[0][0], bh[0][1]);
                MMA_TF32(aZ[mf], ah0, ah1, ah2, ah3, bh[1][0], bh[1][1]);
                MMA_TF32(aNs,    ah0, ah1, ah2, ah3, bh[2][0], bh[2][1]);
                MMA_TF32(aR[mf], ah0, ah1, ah2, ah3, bl[0][0], bl[0][1]);
                MMA_TF32(aZ[mf], ah0, ah1, ah2, ah3, bl[1][0], bl[1][1]);
                MMA_TF32(aNs,    ah0, ah1, ah2, ah3, bl[2][0], bl[2][1]);
                MMA_TF32(aR[mf], al0, al1, al2, al3, bh[0][0], bh[0][1]);
                MMA_TF32(aZ[mf], al0, al1, al2, al3, bh[1][0], bh[1][1]);
                MMA_TF32(aNs,    al0, al1, al2, al3, bh[2][0], bh[2][1]);
            }
        };

        // ---- prologue ----
        ldgA(0);
        stsA(0);
        ldgA(1);
        ldB(0, 0); ldB(1, 1); ldB(2, 2);
        asm volatile("bar.sync %0, 128;" :: "r"(ks + 1) : "memory");

        #pragma unroll 1
        for (int c = 0; c < NCH; c++) {
            const int buf = c & 1;
            if (c + 1 < NCH) stsA((c + 1) & 1);
            if (c + 2 < NCH) ldgA(c + 2);
            const float2* Abuf = Asplit + buf * AST_BUF;
            #pragma unroll
            for (int jj = 0; jj < 2; jj++) {
                const int j = c * 2 + jj;               // kstep within split, 0..19
                const bool isH = (ks < 3) || (j < 4);   // ks3: k=480+8j, h while <512
                do_kstep(jj, Abuf, bb[j % 3], isH);
                if (j + 3 < 20) ldB(j + 3, (j + 3) % 3);
            }
            asm volatile("bar.sync %0, 128;" :: "r"(ks + 1) : "memory");
        }

        // ---- 4-way K-split tree reduction (reuses staging smem) ----
        __syncthreads();
        float4* R = (float4*)sm;                       // 2 regions x 128 slots x 8
        const int slot = ((w & 3) * 32 + lane) * 8;    // (bg,hf,lane) key
        auto dump = [&](float4* Rg) {
            Rg[slot + 0] = *(float4*)aR[0];  Rg[slot + 1] = *(float4*)aR[1];
            Rg[slot + 2] = *(float4*)aZ[0];  Rg[slot + 3] = *(float4*)aZ[1];
            Rg[slot + 4] = *(float4*)aN[0];  Rg[slot + 5] = *(float4*)aN[1];
            Rg[slot + 6] = *(float4*)aNx[0]; Rg[slot + 7] = *(float4*)aNx[1];
        };
        auto gather = [&](const float4* Rg) {
            auto addf4 = [](float* a, float4 v) {
                a[0] += v.x; a[1] += v.y; a[2] += v.z; a[3] += v.w;
            };
            addf4(aR[0],  Rg[slot + 0]); addf4(aR[1],  Rg[slot + 1]);
            addf4(aZ[0],  Rg[slot + 2]); addf4(aZ[1],  Rg[slot + 3]);
            addf4(aN[0],  Rg[slot + 4]); addf4(aN[1],  Rg[slot + 5]);
            addf4(aNx[0], Rg[slot + 6]); addf4(aNx[1], Rg[slot + 7]);
        };

        if (ks == 2) dump(R);
        if (ks == 3) dump(R + 1024);
        __syncthreads();
        if (ks == 0) gather(R);
        if (ks == 1) gather(R + 1024);
        __syncthreads();
        if (ks == 1) dump(R);
        __syncthreads();

        if (ks == 0) {
            gather(R);

            // ---- gates epilogue ----
            #pragma unroll
            for (int mf = 0; mf < 2; mf++) {
                #pragma unroll
                for (int rh = 0; rh < 2; rh++) {
                    const int b = b0 + bg * 32 + mf * 16 + (lane >> 2) + rh * 8;
                    const int i0 = rh * 2;
                    float2 hp = __ldcg((const float2*)(hsrc + (size_t)b * Hh + mcol));

                    float rl = sigf(aR[mf][i0]     + cR.x);
                    float rr = sigf(aR[mf][i0 + 1] + cR.y);
                    float zl = sigf(aZ[mf][i0]     + cZ.x);
                    float zr = sigf(aZ[mf][i0 + 1] + cZ.y);
                    float nl = tanhf(aNx[mf][i0]     + cNx.x + rl * (aN[mf][i0]     + cNh.x));
                    float nr = tanhf(aNx[mf][i0 + 1] + cNx.y + rr * (aN[mf][i0 + 1] + cNh.y));

                    float hl = (1.f - zl) * nl + zl * hp.x;
                    float hr = (1.f - zr) * nr + zr * hp.y;
                    hl = fminf(fmaxf(hl, -CLIPV), CLIPV);
                    hr = fminf(fmaxf(hr, -CLIPV), CLIPV);

                    float2 res = make_float2(hl, hr);
                    __stcg((float2*)(hdst + (size_t)b * Hh + mcol), res);
                    *(float2*)(out + ((size_t)b * Tt + t) * Hh + mcol) = res;
                    if (t == Tt - 1)
                        *(float2*)(out + (size_t)Bsz * Tt * Hh + (size_t)b * Hh + mcol) = res;
                }
            }
        }

        // ---- grid barrier (monotonic phase, wrap-safe) ----
        __syncthreads();
        if (tid == 0) {
            __threadfence();
            unsigned old = atomicAdd(&g_cnt, 1u);
            if (old == (unsigned)(NBLK - 1)) {
                atomicExch(&g_cnt, 0u);
                __threadfence();
                atomicAdd(&g_phase, 1u);
            } else {
                const unsigned tgt = bar_base + (unsigned)(t + 1);
                unsigned v;
                do {
                    __nanosleep(32);
                    asm volatile("ld.global.cg.u32 %0, [%1];" : "=r"(v) : "l"(&g_phase));
                } while ((int)(v - tgt) < 0);
            }
            __threadfence();
        }
        __syncthreads();
    }
}

extern "C" void kernel_launch(void* const* d_in, const int* in_sizes, int n_in,
                              void* d_out, int out_size)
{
    (void)in_sizes; (void)n_in; (void)out_size;
    const float* x    = (const float*)d_in[0];
    const float* h0   = (const float*)d_in[1];
    const float* w_ih = (const float*)d_in[2];
    const float* w_hh = (const float*)d_in[3];
    const float* b_ih = (const float*)d_in[4];
    const float* b_hh = (const float*)d_in[5];
    float* out = (float*)d_out;

    cudaFuncSetAttribute(gru_persist, cudaFuncAttributeMaxDynamicSharedMemorySize,
                         SMEM_BYTES);

    pack_w<<<(3 * 64 * 80 * 32 + 255) / 256, 256>>>(w_ih, w_hh);
    gru_persist<<<NBLK, NTHR, SMEM_BYTES>>>(x, h0, b_ih, b_hh, out);
}

// round 13
// speedup vs baseline: 1.0894x; 1.0894x over previous
#include <cuda_runtime.h>
#include <cuda_bf16.h>
#include <cstdint>
#include <math.h>

#define Bsz 256
#define Tt  500
#define Ii  128
#define Hh  512
#define CLIPV 5.0f

#define NTHR 256
// smem: B fragments [40 kstep][3 gate][32 lane] uint4 = 61440
//       A staging  [2 buf][2 plane][128 row][80B]    = 40960
#define WB_U4 3840
#define SM_A  61440
#define PLANE 10240
#define BUFSZ (2*PLANE)
#define SMEM_BYTES (SM_A + 2*BUFSZ)    // 102400

// pre-swizzled bf16 hi/lo plane images
__device__ __align__(16) unsigned char g_himg[2][2][2][128][1024];  // [phase][bt][plane][row][512k*2B]
__device__ __align__(16) unsigned char g_ximg[Tt][2][2][128][256];  // [t][bt][plane][row][128k*2B]
__device__ __align__(16) uint4 g_wb[64 * WB_U4];                    // [nt][kstep][gate][lane]

__device__ __forceinline__ uint32_t smem_u32(const void* p) {
    uint32_t a;
    asm("{ .reg .u64 t; cvta.to.shared.u64 t, %1; cvt.u32.u64 %0, t; }" : "=r"(a) : "l"(p));
    return a;
}
__device__ __forceinline__ void bf16hl(float v, unsigned short& hi, unsigned short& lo) {
    __nv_bfloat16 h = __float2bfloat16_rn(v);
    __nv_bfloat16 l = __float2bfloat16_rn(v - __bfloat162float(h));
    hi = __bfloat16_as_ushort(h);
    lo = __bfloat16_as_ushort(l);
}
__device__ __forceinline__ float sigf(float x) { return 1.f / (1.f + __expf(-x)); }

#define MMA_BF16(D, A0, A1, A2, A3, B0, B1)                               \
    asm volatile("mma.sync.aligned.m16n8k16.row.col.f32.bf16.bf16.f32 "   \
                 "{%0,%1,%2,%3},{%4,%5,%6,%7},{%8,%9},{%0,%1,%2,%3};"     \
                 : "+f"(D[0]), "+f"(D[1]), "+f"(D[2]), "+f"(D[3])         \
                 : "r"(A0), "r"(A1), "r"(A2), "r"(A3), "r"(B0), "r"(B1))

#define LDSM4(R0, R1, R2, R3, ADDR)                                       \
    asm volatile("ldmatrix.sync.aligned.m8n8.x4.shared.b16 {%0,%1,%2,%3}, [%4];" \
                 : "=r"(R0), "=r"(R1), "=r"(R2), "=r"(R3) : "r"(ADDR))

// ---------------- one-time pre-kernels (idempotent, run every call) ----------------
__global__ void conv_x(const float* __restrict__ x) {
    int idx = blockIdx.x * 256 + threadIdx.x;        // Tt*16 blocks
    int oct = idx & 15, b = (idx >> 4) & 255, t = idx >> 12;
    if (t >= Tt) return;
    int k0 = oct * 8, bt = b >> 7, row = b & 127;
    const float* p = x + ((size_t)b * Tt + t) * Ii + k0;
    float4 v0 = __ldcg((const float4*)p), v1 = __ldcg((const float4*)(p + 4));
    float vs[8] = {v0.x, v0.y, v0.z, v0.w, v1.x, v1.y, v1.z, v1.w};
    unsigned short h[8], l[8];
    #pragma unroll
    for (int e = 0; e < 8; e++) bf16hl(vs[e], h[e], l[e]);
    uint4 hv = make_uint4(h[0]|(unsigned)h[1]<<16, h[2]|(unsigned)h[3]<<16,
                          h[4]|(unsigned)h[5]<<16, h[6]|(unsigned)h[7]<<16);
    uint4 lv = make_uint4(l[0]|(unsigned)l[1]<<16, l[2]|(unsigned)l[3]<<16,
                          l[4]|(unsigned)l[5]<<16, l[6]|(unsigned)l[7]<<16);
    *(uint4*)&g_ximg[t][bt][0][row][k0 * 2] = hv;
    *(uint4*)&g_ximg[t][bt][1][row][k0 * 2] = lv;
}

__global__ void conv_h0(const float* __restrict__ h0) {
    int idx = blockIdx.x * 256 + threadIdx.x;        // 2*128*64 threads
    int oct = idx & 63, row = (idx >> 6) & 127, bt = idx >> 13;
    int k0 = oct * 8;
    const float* p = h0 + (size_t)(bt * 128 + row) * Hh + k0;
    float4 v0 = __ldcg((const float4*)p), v1 = __ldcg((const float4*)(p + 4));
    float vs[8] = {v0.x, v0.y, v0.z, v0.w, v1.x, v1.y, v1.z, v1.w};
    unsigned short h[8], l[8];
    #pragma unroll
    for (int e = 0; e < 8; e++) bf16hl(vs[e], h[e], l[e]);
    uint4 hv = make_uint4(h[0]|(unsigned)h[1]<<16, h[2]|(unsigned)h[3]<<16,
                          h[4]|(unsigned)h[5]<<16, h[6]|(unsigned)h[7]<<16);
    uint4 lv = make_uint4(l[0]|(unsigned)l[1]<<16, l[2]|(unsigned)l[3]<<16,
                          l[4]|(unsigned)l[5]<<16, l[6]|(unsigned)l[7]<<16);
    *(uint4*)&g_himg[0][bt][0][row][k0 * 2] = hv;
    *(uint4*)&g_himg[0][bt][1][row][k0 * 2] = lv;
}

// weights -> per-lane bf16 hi/lo m16n8k16 B fragments (R7-validated map, bf16 k16)
__global__ void pack_w(const float* __restrict__ w_ih, const float* __restrict__ w_hh) {
    int idx = blockIdx.x * 256 + threadIdx.x;        // 64*40*32
    if (idx >= 64 * 40 * 32) return;
    int lane = idx & 31, kstep = (idx >> 5) % 40, nt = idx / (32 * 40);
    int kb = kstep * 16 + 2 * (lane & 3);
    #pragma unroll
    for (int g = 0; g < 3; g++) {
        int n = g * Hh + nt * 8 + (lane >> 2);
        float v[4];
        #pragma unroll
        for (int e = 0; e < 4; e++) {
            int k = kb + (e >> 1) * 8 + (e & 1);     // kb, kb+1, kb+8, kb+9
            v[e] = (k < Hh) ? w_hh[(size_t)n * Hh + k] : w_ih[(size_t)n * Ii + (k - Hh)];
        }
        unsigned short h[4], l[4];
        #pragma unroll
        for (int e = 0; e < 4; e++) bf16hl(v[e], h[e], l[e]);
        g_wb[(size_t)((nt * 40 + kstep) * 3 + g) * 32 + lane] =
            make_uint4(h[0]|(unsigned)h[1]<<16, h[2]|(unsigned)h[3]<<16,
                       l[0]|(unsigned)l[1]<<16, l[2]|(unsigned)l[3]<<16);
    }
}

// ---------------- one GRU timestep ----------------
// grid (64 nt, 2 bt) x 256 threads. Warp w owns batch rows w*16..w*16+15,
// all 24 outputs (3 gates x n8), full K=640 (40 k16-steps). bf16x3 terms.
__global__ void __launch_bounds__(NTHR, 1) gru_step(
    int t,
    const float* __restrict__ h0,
    const float* __restrict__ b_ih,
    const float* __restrict__ b_hh,
    float* __restrict__ out)
{
    extern __shared__ char smx[];
    const uint32_t smb = smem_u32(smx);

    const int tid = threadIdx.x, lane = tid & 31, w = tid >> 5;
    const int nt = blockIdx.x, bt = blockIdx.y;
    const int ph = t & 1;

    // B fragments -> smem (60 KB from L2-resident pack)
    {
        const uint4* src = g_wb + (size_t)nt * WB_U4;
        uint4* dst = (uint4*)smx;
        #pragma unroll
        for (int i = 0; i < 15; i++) dst[tid + i * 256] = __ldcg(src + tid + i * 256);
    }

    __align__(16) float aR[4], aZ[4], aN[4], aNx[4];
    #pragma unroll
    for (int i = 0; i < 4; i++) { aR[i] = 0.f; aZ[i] = 0.f; aN[i] = 0.f; aNx[i] = 0.f; }

    // staging mapping: plane p = tid>>7, row = tid&127, 64B per thread per chunk
    const int sp = tid >> 7, srw = tid & 127;

    auto stage = [&](int c, int buf) {               // chunk c: k [c*32, c*32+32)
        const int k0 = c * 32;
        const unsigned char* s = (k0 < Hh)
            ? &g_himg[ph][bt][sp][srw][k0 * 2]
            : &g_ximg[t][bt][sp][srw][(k0 - Hh) * 2];
        unsigned char* d = (unsigned char*)smx + SM_A + buf * BUFSZ + sp * PLANE + srw * 80;
        #pragma unroll
        for (int i = 0; i < 4; i++)
            *(uint4*)(d + i * 16) = __ldcg((const uint4*)(s + i * 16));
    };

    auto compute = [&](int j, int buf) {             // kstep j (0..39)
        const bool isH = (j < 32);
        const uint4* Bs = (const uint4*)smx;
        uint4 b0 = Bs[(j * 3 + 0) * 32 + lane];
        uint4 b1 = Bs[(j * 3 + 1) * 32 + lane];
        uint4 b2 = Bs[(j * 3 + 2) * 32 + lane];
        const uint32_t pb  = smb + SM_A + buf * BUFSZ;
        const uint32_t lad = w * 1280 + (lane & 15) * 80 + (lane >> 4) * 16 + (j & 1) * 32;
        uint32_t ah0, ah1, ah2, ah3, al0, al1, al2, al3;
        LDSM4(ah0, ah1, ah2, ah3, pb + lad);
        LDSM4(al0, al1, al2, al3, pb + PLANE + lad);
        float* DN = isH ? aN : aNx;
        MMA_BF16(aR, ah0, ah1, ah2, ah3, b0.x, b0.y);
        MMA_BF16(aZ, ah0, ah1, ah2, ah3, b1.x, b1.y);
        MMA_BF16(DN, ah0, ah1, ah2, ah3, b2.x, b2.y);
        MMA_BF16(aR, ah0, ah1, ah2, ah3, b0.z, b0.w);
        MMA_BF16(aZ, ah0, ah1, ah2, ah3, b1.z, b1.w);
        MMA_BF16(DN, ah0, ah1, ah2, ah3, b2.z, b2.w);
        MMA_BF16(aR, al0, al1, al2, al3, b0.x, b0.y);
        MMA_BF16(aZ, al0, al1, al2, al3, b1.x, b1.y);
        MMA_BF16(DN, al0, al1, al2, al3, b2.x, b2.y);
    };

    stage(0, 0);
    __syncthreads();
    #pragma unroll 1
    for (int c = 0; c < 20; c++) {
        if (c + 1 < 20) stage(c + 1, (c + 1) & 1);
        compute(2 * c,     c & 1);
        compute(2 * c + 1, c & 1);
        __syncthreads();
    }

    // ---- gates epilogue: each thread 2 rows x 2 cols ----
    const int mg = nt * 8 + 2 * (lane & 3);
    const float2 cR  = make_float2(b_ih[mg] + b_hh[mg], b_ih[mg+1] + b_hh[mg+1]);
    const float2 cZ  = make_float2(b_ih[Hh+mg] + b_hh[Hh+mg], b_ih[Hh+mg+1] + b_hh[Hh+mg+1]);
    const float2 cNx = make_float2(b_ih[2*Hh+mg], b_ih[2*Hh+mg+1]);
    const float2 cNh = make_float2(b_hh[2*Hh+mg], b_hh[2*Hh+mg+1]);

    #pragma unroll
    for (int rr = 0; rr < 2; rr++) {
        const int lrow = w * 16 + (lane >> 2) + rr * 8;   // 0..127
        const int row  = bt * 128 + lrow;                 // global batch
        const int i0 = rr * 2;

        float2 hpv = (t == 0)
            ? *(const float2*)(h0 + (size_t)row * Hh + mg)
            : *(const float2*)(out + ((size_t)row * Tt + (t - 1)) * Hh + mg);

        float rl = sigf(aR[i0]   + cR.x);
        float rh = sigf(aR[i0+1] + cR.y);
        float zl = sigf(aZ[i0]   + cZ.x);
        float zh = sigf(aZ[i0+1] + cZ.y);
        float nl = tanhf(aNx[i0]   + cNx.x + rl * (aN[i0]   + cNh.x));
        float nh = tanhf(aNx[i0+1] + cNx.y + rh * (aN[i0+1] + cNh.y));
        float hl = (1.f - zl) * nl + zl * hpv.x;
        float hh = (1.f - zh) * nh + zh * hpv.y;
        hl = fminf(fmaxf(hl, -CLIPV), CLIPV);
        hh = fminf(fmaxf(hh, -CLIPV), CLIPV);

        *(float2*)(out + ((size_t)row * Tt + t) * Hh + mg) = make_float2(hl, hh);
        if (t == Tt - 1)
            *(float2*)(out + (size_t)Bsz * Tt * Hh + (size_t)row * Hh + mg)
                = make_float2(hl, hh);

        // h image for next step (kernel boundary orders visibility)
        unsigned short lh, ll, hhh, hhl;
        bf16hl(hl, lh, ll);
        bf16hl(hh, hhh, hhl);
        *(unsigned*)&g_himg[ph ^ 1][bt][0][lrow][mg * 2] = lh | (unsigned)hhh << 16;
        *(unsigned*)&g_himg[ph ^ 1][bt][1][lrow][mg * 2] = ll | (unsigned)hhl << 16;
    }
}

extern "C" void kernel_launch(void* const* d_in, const int* in_sizes, int n_in,
                              void* d_out, int out_size)
{
    (void)in_sizes; (void)n_in; (void)out_size;
    const float* x    = (const float*)d_in[0];
    const float* h0   = (const float*)d_in[1];
    const float* w_ih = (const float*)d_in[2];
    const float* w_hh = (const float*)d_in[3];
    const float* b_ih = (const float*)d_in[4];
    const float* b_hh = (const float*)d_in[5];
    float* out = (float*)d_out;

    cudaFuncSetAttribute(gru_step, cudaFuncAttributeMaxDynamicSharedMemorySize,
                         SMEM_BYTES);

    pack_w<<<(64 * 40 * 32 + 255) / 256, 256>>>(w_ih, w_hh);
    conv_h0<<<(2 * 128 * 64) / 256, 256>>>(h0);
    conv_x<<<Tt * 16, 256>>>(x);

    dim3 grid(64, 2);
    for (int t = 0; t < Tt; t++)
        gru_step<<<grid, NTHR, SMEM_BYTES>>>(t, h0, b_ih, b_hh, out);
}

// round 14
// speedup vs baseline: 1.3076x; 1.2003x over previous
#include <cuda_runtime.h>
#include <cuda_bf16.h>
#include <cstdint>
#include <math.h>

#define Bsz 256
#define Tt  500
#define Ii  128
#define Hh  512
#define CLIPV 5.0f

#define NTHR 256
// smem: B fragments [40 kstep][3 gate][32 lane] uint4 = 61440
//       A staging [2 buf][2 sub][2 plane][128 row][80B] = 81920
#define WB_U4 3840
#define SM_A  61440
#define SUBSZ 10240
#define BUFSZ 40960
#define SMEM_BYTES (SM_A + 2*BUFSZ)    // 143360

// pre-swizzled bf16 hi/lo plane images
__device__ __align__(16) unsigned char g_himg[2][2][2][128][1024];  // [phase][bt][plane][row][512k*2B]
__device__ __align__(16) unsigned char g_ximg[Tt][2][2][128][256];  // [t][bt][plane][row][128k*2B]
__device__ __align__(16) uint4 g_wb[64 * WB_U4];                    // [nt][kstep][gate][lane]

__device__ __forceinline__ uint32_t smem_u32(const void* p) {
    uint32_t a;
    asm("{ .reg .u64 t; cvta.to.shared.u64 t, %1; cvt.u32.u64 %0, t; }" : "=r"(a) : "l"(p));
    return a;
}
__device__ __forceinline__ void bf16hl(float v, unsigned short& hi, unsigned short& lo) {
    __nv_bfloat16 h = __float2bfloat16_rn(v);
    __nv_bfloat16 l = __float2bfloat16_rn(v - __bfloat162float(h));
    hi = __bfloat16_as_ushort(h);
    lo = __bfloat16_as_ushort(l);
}
__device__ __forceinline__ float sigf(float x) { return 1.f / (1.f + __expf(-x)); }

#define MMA_BF16(D, A0, A1, A2, A3, B0, B1)                               \
    asm volatile("mma.sync.aligned.m16n8k16.row.col.f32.bf16.bf16.f32 "   \
                 "{%0,%1,%2,%3},{%4,%5,%6,%7},{%8,%9},{%0,%1,%2,%3};"     \
                 : "+f"(D[0]), "+f"(D[1]), "+f"(D[2]), "+f"(D[3])         \
                 : "r"(A0), "r"(A1), "r"(A2), "r"(A3), "r"(B0), "r"(B1))

#define LDSM4(R0, R1, R2, R3, ADDR)                                       \
    asm volatile("ldmatrix.sync.aligned.m8n8.x4.shared.b16 {%0,%1,%2,%3}, [%4];" \
                 : "=r"(R0), "=r"(R1), "=r"(R2), "=r"(R3) : "r"(ADDR))

// ---------------- one-time pre-kernels (idempotent) ----------------
__global__ void conv_x(const float* __restrict__ x) {
    int idx = blockIdx.x * 256 + threadIdx.x;
    int oct = idx & 15, b = (idx >> 4) & 255, t = idx >> 12;
    if (t >= Tt) return;
    int k0 = oct * 8, bt = b >> 7, row = b & 127;
    const float* p = x + ((size_t)b * Tt + t) * Ii + k0;
    float4 v0 = __ldcg((const float4*)p), v1 = __ldcg((const float4*)(p + 4));
    float vs[8] = {v0.x, v0.y, v0.z, v0.w, v1.x, v1.y, v1.z, v1.w};
    unsigned short h[8], l[8];
    #pragma unroll
    for (int e = 0; e < 8; e++) bf16hl(vs[e], h[e], l[e]);
    uint4 hv = make_uint4(h[0]|(unsigned)h[1]<<16, h[2]|(unsigned)h[3]<<16,
                          h[4]|(unsigned)h[5]<<16, h[6]|(unsigned)h[7]<<16);
    uint4 lv = make_uint4(l[0]|(unsigned)l[1]<<16, l[2]|(unsigned)l[3]<<16,
                          l[4]|(unsigned)l[5]<<16, l[6]|(unsigned)l[7]<<16);
    *(uint4*)&g_ximg[t][bt][0][row][k0 * 2] = hv;
    *(uint4*)&g_ximg[t][bt][1][row][k0 * 2] = lv;
}

__global__ void conv_h0(const float* __restrict__ h0) {
    int idx = blockIdx.x * 256 + threadIdx.x;
    int oct = idx & 63, row = (idx >> 6) & 127, bt = idx >> 13;
    int k0 = oct * 8;
    const float* p = h0 + (size_t)(bt * 128 + row) * Hh + k0;
    float4 v0 = __ldcg((const float4*)p), v1 = __ldcg((const float4*)(p + 4));
    float vs[8] = {v0.x, v0.y, v0.z, v0.w, v1.x, v1.y, v1.z, v1.w};
    unsigned short h[8], l[8];
    #pragma unroll
    for (int e = 0; e < 8; e++) bf16hl(vs[e], h[e], l[e]);
    uint4 hv = make_uint4(h[0]|(unsigned)h[1]<<16, h[2]|(unsigned)h[3]<<16,
                          h[4]|(unsigned)h[5]<<16, h[6]|(unsigned)h[7]<<16);
    uint4 lv = make_uint4(l[0]|(unsigned)l[1]<<16, l[2]|(unsigned)l[3]<<16,
                          l[4]|(unsigned)l[5]<<16, l[6]|(unsigned)l[7]<<16);
    *(uint4*)&g_himg[0][bt][0][row][k0 * 2] = hv;
    *(uint4*)&g_himg[0][bt][1][row][k0 * 2] = lv;
}

__global__ void pack_w(const float* __restrict__ w_ih, const float* __restrict__ w_hh) {
    int idx = blockIdx.x * 256 + threadIdx.x;
    if (idx >= 64 * 40 * 32) return;
    int lane = idx & 31, kstep = (idx >> 5) % 40, nt = idx / (32 * 40);
    int kb = kstep * 16 + 2 * (lane & 3);
    #pragma unroll
    for (int g = 0; g < 3; g++) {
        int n = g * Hh + nt * 8 + (lane >> 2);
        float v[4];
        #pragma unroll
        for (int e = 0; e < 4; e++) {
            int k = kb + (e >> 1) * 8 + (e & 1);
            v[e] = (k < Hh) ? w_hh[(size_t)n * Hh + k] : w_ih[(size_t)n * Ii + (k - Hh)];
        }
        unsigned short h[4], l[4];
        #pragma unroll
        for (int e = 0; e < 4; e++) bf16hl(v[e], h[e], l[e]);
        g_wb[(size_t)((nt * 40 + kstep) * 3 + g) * 32 + lane] =
            make_uint4(h[0]|(unsigned)h[1]<<16, h[2]|(unsigned)h[3]<<16,
                       l[0]|(unsigned)l[1]<<16, l[2]|(unsigned)l[3]<<16);
    }
}

// ---------------- one GRU timestep ----------------
// grid (64 nt, 2 bt) x 256 threads. Warp w: batch rows w*16..+15, all 24 outs,
// K=640 (40 k16-steps, 10 chunks of 64k). bf16x3 with term+parity-split accums.
__global__ void __launch_bounds__(NTHR, 1) gru_step(
    int t,
    const float* __restrict__ h0,
    const float* __restrict__ b_ih,
    const float* __restrict__ b_hh,
    float* __restrict__ out)
{
    extern __shared__ char smx[];
    const uint32_t smb = smem_u32(smx);

    const int tid = threadIdx.x, lane = tid & 31, w = tid >> 5;
    const int nt = blockIdx.x, bt = blockIdx.y;
    const int ph = t & 1;

    // B fragments -> smem (60 KB, L2-resident pack)
    {
        const uint4* src = g_wb + (size_t)nt * WB_U4;
        uint4* dst = (uint4*)smx;
        #pragma unroll
        for (int i = 0; i < 15; i++) dst[tid + i * 256] = __ldcg(src + tid + i * 256);
    }

    // accumulators: [parity][term][4]; term: 0=ah*bh 1=ah*bl 2=al*bh
    __align__(16) float aR[2][3][4], aZ[2][3][4], aN[2][3][4], aNx[2][3][4];
    #pragma unroll
    for (int p = 0; p < 2; p++)
        #pragma unroll
        for (int q = 0; q < 3; q++)
            #pragma unroll
            for (int i = 0; i < 4; i++)
                { aR[p][q][i]=0.f; aZ[p][q][i]=0.f; aN[p][q][i]=0.f; aNx[p][q][i]=0.f; }

    const int sp = tid >> 7, srw = tid & 127;   // staging: plane, row

    auto stage = [&](int c, int buf) {          // chunk c: k [64c, 64c+64)
        const int k0 = c * 64;
        const unsigned char* s = (k0 < Hh)
            ? &g_himg[ph][bt][sp][srw][k0 * 2]
            : &g_ximg[t][bt][sp][srw][(k0 - Hh) * 2];
        unsigned char* d0 = (unsigned char*)smx + SM_A + buf * BUFSZ
                            + sp * SUBSZ + srw * 80;            // sub 0
        unsigned char* d1 = d0 + 2 * SUBSZ;                      // sub 1
        #pragma unroll
        for (int i = 0; i < 4; i++)
            *(uint4*)(d0 + i * 16) = __ldcg((const uint4*)(s + i * 16));
        #pragma unroll
        for (int i = 0; i < 4; i++)
            *(uint4*)(d1 + i * 16) = __ldcg((const uint4*)(s + 64 + i * 16));
    };

    auto compute = [&](int j, int jj, int buf, bool isH) {  // j global kstep, jj=j&3
        const int par = jj & 1;                  // compile-time in unrolled body
        const int sub = (jj >> 1) & 1;
        const uint4* Bs = (const uint4*)smx;
        uint4 b0 = Bs[(j * 3 + 0) * 32 + lane];
        uint4 b1 = Bs[(j * 3 + 1) * 32 + lane];
        uint4 b2 = Bs[(j * 3 + 2) * 32 + lane];
        const uint32_t pb  = smb + SM_A + buf * BUFSZ + sub * (2 * SUBSZ);
        const uint32_t lad = w * 1280 + (lane & 15) * 80 + (lane >> 4) * 16 + par * 32;
        uint32_t ah0, ah1, ah2, ah3, al0, al1, al2, al3;
        LDSM4(ah0, ah1, ah2, ah3, pb + lad);
        LDSM4(al0, al1, al2, al3, pb + SUBSZ + lad);
        float (*DN)[4] = isH ? aN[par] : aNx[par];
        MMA_BF16(aR[par][0], ah0, ah1, ah2, ah3, b0.x, b0.y);
        MMA_BF16(aZ[par][0], ah0, ah1, ah2, ah3, b1.x, b1.y);
        MMA_BF16(DN[0],      ah0, ah1, ah2, ah3, b2.x, b2.y);
        MMA_BF16(aR[par][1], ah0, ah1, ah2, ah3, b0.z, b0.w);
        MMA_BF16(aZ[par][1], ah0, ah1, ah2, ah3, b1.z, b1.w);
        MMA_BF16(DN[1],      ah0, ah1, ah2, ah3, b2.z, b2.w);
        MMA_BF16(aR[par][2], al0, al1, al2, al3, b0.x, b0.y);
        MMA_BF16(aZ[par][2], al0, al1, al2, al3, b1.x, b1.y);
        MMA_BF16(DN[2],      al0, al1, al2, al3, b2.x, b2.y);
    };

    stage(0, 0);
    __syncthreads();
    #pragma unroll 1
    for (int c = 0; c < 10; c++) {
        const int buf = c & 1;
        if (c + 1 < 10) stage(c + 1, (c + 1) & 1);
        const bool isH = (c < 8);
        #pragma unroll
        for (int jj = 0; jj < 4; jj++)
            compute(4 * c + jj, jj, buf, isH);
        __syncthreads();
    }

    // ---- gates epilogue ----
    const int mg = nt * 8 + 2 * (lane & 3);
    const float2 cR  = make_float2(b_ih[mg] + b_hh[mg], b_ih[mg+1] + b_hh[mg+1]);
    const float2 cZ  = make_float2(b_ih[Hh+mg] + b_hh[Hh+mg], b_ih[Hh+mg+1] + b_hh[Hh+mg+1]);
    const float2 cNx = make_float2(b_ih[2*Hh+mg], b_ih[2*Hh+mg+1]);
    const float2 cNh = make_float2(b_hh[2*Hh+mg], b_hh[2*Hh+mg+1]);

    float sR[4], sZ[4], sN[4], sNx[4];
    #pragma unroll
    for (int i = 0; i < 4; i++) {
        sR[i]  = (aR[0][0][i] + aR[0][1][i]) + (aR[0][2][i] + aR[1][0][i])
               + (aR[1][1][i] + aR[1][2][i]);
        sZ[i]  = (aZ[0][0][i] + aZ[0][1][i]) + (aZ[0][2][i] + aZ[1][0][i])
               + (aZ[1][1][i] + aZ[1][2][i]);
        sN[i]  = (aN[0][0][i] + aN[0][1][i]) + (aN[0][2][i] + aN[1][0][i])
               + (aN[1][1][i] + aN[1][2][i]);
        sNx[i] = (aNx[0][0][i] + aNx[0][1][i]) + (aNx[0][2][i] + aNx[1][0][i])
               + (aNx[1][1][i] + aNx[1][2][i]);
    }

    #pragma unroll
    for (int rr = 0; rr < 2; rr++) {
        const int lrow = w * 16 + (lane >> 2) + rr * 8;
        const int row  = bt * 128 + lrow;
        const int i0 = rr * 2;

        float2 hpv = (t == 0)
            ? *(const float2*)(h0 + (size_t)row * Hh + mg)
            : *(const float2*)(out + ((size_t)row * Tt + (t - 1)) * Hh + mg);

        float rl = sigf(sR[i0]   + cR.x);
        float rh = sigf(sR[i0+1] + cR.y);
        float zl = sigf(sZ[i0]   + cZ.x);
        float zh = sigf(sZ[i0+1] + cZ.y);
        float nl = tanhf(sNx[i0]   + cNx.x + rl * (sN[i0]   + cNh.x));
        float nh = tanhf(sNx[i0+1] + cNx.y + rh * (sN[i0+1] + cNh.y));
        float hl = (1.f - zl) * nl + zl * hpv.x;
        float hh = (1.f - zh) * nh + zh * hpv.y;
        hl = fminf(fmaxf(hl, -CLIPV), CLIPV);
        hh = fminf(fmaxf(hh, -CLIPV), CLIPV);

        *(float2*)(out + ((size_t)row * Tt + t) * Hh + mg) = make_float2(hl, hh);
        if (t == Tt - 1)
            *(float2*)(out + (size_t)Bsz * Tt * Hh + (size_t)row * Hh + mg)
                = make_float2(hl, hh);

        unsigned short lh, ll, hhh, hhl;
        bf16hl(hl, lh, ll);
        bf16hl(hh, hhh, hhl);
        *(unsigned*)&g_himg[ph ^ 1][bt][0][lrow][mg * 2] = lh | (unsigned)hhh << 16;
        *(unsigned*)&g_himg[ph ^ 1][bt][1][lrow][mg * 2] = ll | (unsigned)hhl << 16;
    }
}

extern "C" void kernel_launch(void* const* d_in, const int* in_sizes, int n_in,
                              void* d_out, int out_size)
{
    (void)in_sizes; (void)n_in; (void)out_size;
    const float* x    = (const float*)d_in[0];
    const float* h0   = (const float*)d_in[1];
    const float* w_ih = (const float*)d_in[2];
    const float* w_hh = (const float*)d_in[3];
    const float* b_ih = (const float*)d_in[4];
    const float* b_hh = (const float*)d_in[5];
    float* out = (float*)d_out;

    cudaFuncSetAttribute(gru_step, cudaFuncAttributeMaxDynamicSharedMemorySize,
                         SMEM_BYTES);

    pack_w<<<(64 * 40 * 32 + 255) / 256, 256>>>(w_ih, w_hh);
    conv_h0<<<(2 * 128 * 64) / 256, 256>>>(h0);
    conv_x<<<Tt * 16, 256>>>(x);

    dim3 grid(64, 2);
    for (int t = 0; t < Tt; t++)
        gru_step<<<grid, NTHR, SMEM_BYTES>>>(t, h0, b_ih, b_hh, out);
}

// round 15
// speedup vs baseline: 2.7550x; 2.1069x over previous
#include <cuda_runtime.h>
#include <cuda_bf16.h>
#include <cstdint>
#include <math.h>

#define Bsz 256
#define Tt  500
#define Ii  128
#define Hh  512
#define CLIPV 5.0f

#define NTHR 256
// smem: B fragments [40 kstep][3 gate][32 lane] uint4 = 61440
//       A rings: 8 warps x 4 slots x (2 sub x 2 plane x 16 row x 80B) = 163840
#define WB_U4  3840
#define SM_A   61440
#define WRING  20480      // per-warp ring (4 slots x 5120)
#define SLOT   5120
#define SMEM_BYTES (SM_A + 8 * WRING)   // 225280

// pre-swizzled bf16 hi/lo plane images
__device__ __align__(16) unsigned char g_himg[2][2][2][128][1024];  // [phase][bt][plane][row][512k*2B]
__device__ __align__(16) unsigned char g_ximg[Tt][2][2][128][256];  // [t][bt][plane][row][128k*2B]
__device__ __align__(16) uint4 g_wb[64 * WB_U4];                    // [nt][kstep][gate][lane]

__device__ __forceinline__ uint32_t smem_u32(const void* p) {
    uint32_t a;
    asm("{ .reg .u64 t; cvta.to.shared.u64 t, %1; cvt.u32.u64 %0, t; }" : "=r"(a) : "l"(p));
    return a;
}
__device__ __forceinline__ void bf16hl(float v, unsigned short& hi, unsigned short& lo) {
    __nv_bfloat16 h = __float2bfloat16_rn(v);
    __nv_bfloat16 l = __float2bfloat16_rn(v - __bfloat162float(h));
    hi = __bfloat16_as_ushort(h);
    lo = __bfloat16_as_ushort(l);
}
__device__ __forceinline__ float sigf(float x) { return 1.f / (1.f + __expf(-x)); }
__device__ __forceinline__ void cp16(uint32_t dst, const void* src) {
    asm volatile("cp.async.cg.shared.global [%0], [%1], 16;"
                 :: "r"(dst), "l"(src) : "memory");
}

#define MMA_BF16(D, A0, A1, A2, A3, B0, B1)                               \
    asm volatile("mma.sync.aligned.m16n8k16.row.col.f32.bf16.bf16.f32 "   \
                 "{%0,%1,%2,%3},{%4,%5,%6,%7},{%8,%9},{%0,%1,%2,%3};"     \
                 : "+f"(D[0]), "+f"(D[1]), "+f"(D[2]), "+f"(D[3])         \
                 : "r"(A0), "r"(A1), "r"(A2), "r"(A3), "r"(B0), "r"(B1))

#define LDSM4(R0, R1, R2, R3, ADDR)                                       \
    asm volatile("ldmatrix.sync.aligned.m8n8.x4.shared.b16 {%0,%1,%2,%3}, [%4];" \
                 : "=r"(R0), "=r"(R1), "=r"(R2), "=r"(R3) : "r"(ADDR))

// ---------------- one-time pre-kernels (idempotent) ----------------
__global__ void conv_x(const float* __restrict__ x) {
    int idx = blockIdx.x * 256 + threadIdx.x;
    int oct = idx & 15, b = (idx >> 4) & 255, t = idx >> 12;
    if (t >= Tt) return;
    int k0 = oct * 8, bt = b >> 7, row = b & 127;
    const float* p = x + ((size_t)b * Tt + t) * Ii + k0;
    float4 v0 = __ldcg((const float4*)p), v1 = __ldcg((const float4*)(p + 4));
    float vs[8] = {v0.x, v0.y, v0.z, v0.w, v1.x, v1.y, v1.z, v1.w};
    unsigned short h[8], l[8];
    #pragma unroll
    for (int e = 0; e < 8; e++) bf16hl(vs[e], h[e], l[e]);
    uint4 hv = make_uint4(h[0]|(unsigned)h[1]<<16, h[2]|(unsigned)h[3]<<16,
                          h[4]|(unsigned)h[5]<<16, h[6]|(unsigned)h[7]<<16);
    uint4 lv = make_uint4(l[0]|(unsigned)l[1]<<16, l[2]|(unsigned)l[3]<<16,
                          l[4]|(unsigned)l[5]<<16, l[6]|(unsigned)l[7]<<16);
    *(uint4*)&g_ximg[t][bt][0][row][k0 * 2] = hv;
    *(uint4*)&g_ximg[t][bt][1][row][k0 * 2] = lv;
}

__global__ void conv_h0(const float* __restrict__ h0) {
    int idx = blockIdx.x * 256 + threadIdx.x;
    int oct = idx & 63, row = (idx >> 6) & 127, bt = idx >> 13;
    int k0 = oct * 8;
    const float* p = h0 + (size_t)(bt * 128 + row) * Hh + k0;
    float4 v0 = __ldcg((const float4*)p), v1 = __ldcg((const float4*)(p + 4));
    float vs[8] = {v0.x, v0.y, v0.z, v0.w, v1.x, v1.y, v1.z, v1.w};
    unsigned short h[8], l[8];
    #pragma unroll
    for (int e = 0; e < 8; e++) bf16hl(vs[e], h[e], l[e]);
    uint4 hv = make_uint4(h[0]|(unsigned)h[1]<<16, h[2]|(unsigned)h[3]<<16,
                          h[4]|(unsigned)h[5]<<16, h[6]|(unsigned)h[7]<<16);
    uint4 lv = make_uint4(l[0]|(unsigned)l[1]<<16, l[2]|(unsigned)l[3]<<16,
                          l[4]|(unsigned)l[5]<<16, l[6]|(unsigned)l[7]<<16);
    *(uint4*)&g_himg[0][bt][0][row][k0 * 2] = hv;
    *(uint4*)&g_himg[0][bt][1][row][k0 * 2] = lv;
}

__global__ void pack_w(const float* __restrict__ w_ih, const float* __restrict__ w_hh) {
    int idx = blockIdx.x * 256 + threadIdx.x;
    if (idx >= 64 * 40 * 32) return;
    int lane = idx & 31, kstep = (idx >> 5) % 40, nt = idx / (32 * 40);
    int kb = kstep * 16 + 2 * (lane & 3);
    #pragma unroll
    for (int g = 0; g < 3; g++) {
        int n = g * Hh + nt * 8 + (lane >> 2);
        float v[4];
        #pragma unroll
        for (int e = 0; e < 4; e++) {
            int k = kb + (e >> 1) * 8 + (e & 1);
            v[e] = (k < Hh) ? w_hh[(size_t)n * Hh + k] : w_ih[(size_t)n * Ii + (k - Hh)];
        }
        unsigned short h[4], l[4];
        #pragma unroll
        for (int e = 0; e < 4; e++) bf16hl(v[e], h[e], l[e]);
        g_wb[(size_t)((nt * 40 + kstep) * 3 + g) * 32 + lane] =
            make_uint4(h[0]|(unsigned)h[1]<<16, h[2]|(unsigned)h[3]<<16,
                       l[0]|(unsigned)l[1]<<16, l[2]|(unsigned)l[3]<<16);
    }
}

// ---------------- one GRU timestep ----------------
// grid (64 nt, 2 bt) x 256 threads. Warp w: batch rows 16w..16w+15, all 24 outs,
// K=640 (40 k16-steps, 10 chunks of 64k). Warp-private cp.async staging,
// NO intra-step barriers. bf16x3 with term+parity-split accumulators.
__global__ void __launch_bounds__(NTHR, 1) gru_step(
    int t,
    const float* __restrict__ h0,
    const float* __restrict__ b_ih,
    const float* __restrict__ b_hh,
    float* __restrict__ out)
{
    extern __shared__ char smx[];
    const uint32_t smb = smem_u32(smx);

    const int tid = threadIdx.x, lane = tid & 31, w = tid >> 5;
    const int nt = blockIdx.x, bt = blockIdx.y;
    const int ph = t & 1;

    // B fragments -> smem (cooperative; the ONLY block barrier)
    {
        const uint4* src = g_wb + (size_t)nt * WB_U4;
        uint4* dst = (uint4*)smx;
        #pragma unroll
        for (int i = 0; i < 15; i++) dst[tid + i * 256] = __ldcg(src + tid + i * 256);
    }

    // accumulators: [parity][term][4]
    __align__(16) float aR[2][3][4], aZ[2][3][4], aN[2][3][4], aNx[2][3][4];
    #pragma unroll
    for (int p = 0; p < 2; p++)
        #pragma unroll
        for (int q = 0; q < 3; q++)
            #pragma unroll
            for (int i = 0; i < 4; i++)
                { aR[p][q][i]=0.f; aZ[p][q][i]=0.f; aN[p][q][i]=0.f; aNx[p][q][i]=0.f; }

    const uint32_t wring = smb + SM_A + w * WRING;

    // per-lane decode for the 8 cp.async of a chunk: i = lane + 32q over
    // (s:1)(p:1)(row:4)(col16:2)
    auto cp_chunk = [&](int c) {
        const int k0 = c * 64;
        const uint32_t slot = wring + (c & 3) * SLOT;
        #pragma unroll
        for (int q = 0; q < 8; q++) {
            const int i = lane + 32 * q;
            const int col4 = i & 3, row = (i >> 2) & 15, p = (i >> 6) & 1, s = i >> 7;
            const int grow = w * 16 + row;
            const unsigned char* src = (k0 < Hh)
                ? &g_himg[ph][bt][p][grow][(k0 + s * 32) * 2 + col4 * 16]
                : &g_ximg[t][bt][p][grow][(k0 - Hh + s * 32) * 2 + col4 * 16];
            cp16(slot + s * 2560 + p * 1280 + row * 80 + col4 * 16, src);
        }
        asm volatile("cp.async.commit_group;" ::: "memory");
    };

    auto compute = [&](int j, int jj, bool isH) {   // j global kstep, jj = j&3
        const int par = jj & 1;
        const int sub = (jj >> 1) & 1;
        const uint4* Bs = (const uint4*)smx;
        uint4 b0 = Bs[(j * 3 + 0) * 32 + lane];
        uint4 b1 = Bs[(j * 3 + 1) * 32 + lane];
        uint4 b2 = Bs[(j * 3 + 2) * 32 + lane];
        const uint32_t pb  = wring + ((j >> 2) & 3) * SLOT + sub * 2560;
        const uint32_t lad = (lane & 15) * 80 + (lane >> 4) * 16 + par * 32;
        uint32_t ah0, ah1, ah2, ah3, al0, al1, al2, al3;
        LDSM4(ah0, ah1, ah2, ah3, pb + lad);
        LDSM4(al0, al1, al2, al3, pb + 1280 + lad);
        float (*DN)[4] = isH ? aN[par] : aNx[par];
        MMA_BF16(aR[par][0], ah0, ah1, ah2, ah3, b0.x, b0.y);
        MMA_BF16(aZ[par][0], ah0, ah1, ah2, ah3, b1.x, b1.y);
        MMA_BF16(DN[0],      ah0, ah1, ah2, ah3, b2.x, b2.y);
        MMA_BF16(aR[par][1], ah0, ah1, ah2, ah3, b0.z, b0.w);
        MMA_BF16(aZ[par][1], ah0, ah1, ah2, ah3, b1.z, b1.w);
        MMA_BF16(DN[1],      ah0, ah1, ah2, ah3, b2.z, b2.w);
        MMA_BF16(aR[par][2], al0, al1, al2, al3, b0.x, b0.y);
        MMA_BF16(aZ[par][2], al0, al1, al2, al3, b1.x, b1.y);
        MMA_BF16(DN[2],      al0, al1, al2, al3, b2.x, b2.y);
    };

    // prologue: 3 chunks in flight
    cp_chunk(0);
    cp_chunk(1);
    cp_chunk(2);
    __syncthreads();    // B fragments visible (cp.async unaffected)

    #pragma unroll 1
    for (int c = 0; c < 10; c++) {
        if (c + 3 < 10) cp_chunk(c + 3);
        asm volatile("cp.async.wait_group 3;" ::: "memory");  // chunk c complete
        const bool isH = (c < 8);
        #pragma unroll
        for (int jj = 0; jj < 4; jj++)
            compute(4 * c + jj, jj, isH);
    }

    // ---- gates epilogue ----
    const int mg = nt * 8 + 2 * (lane & 3);
    const float2 cR  = make_float2(b_ih[mg] + b_hh[mg], b_ih[mg+1] + b_hh[mg+1]);
    const float2 cZ  = make_float2(b_ih[Hh+mg] + b_hh[Hh+mg], b_ih[Hh+mg+1] + b_hh[Hh+mg+1]);
    const float2 cNx = make_float2(b_ih[2*Hh+mg], b_ih[2*Hh+mg+1]);
    const float2 cNh = make_float2(b_hh[2*Hh+mg], b_hh[2*Hh+mg+1]);

    float sR[4], sZ[4], sN[4], sNx[4];
    #pragma unroll
    for (int i = 0; i < 4; i++) {
        sR[i]  = (aR[0][0][i] + aR[0][1][i]) + (aR[0][2][i] + aR[1][0][i])
               + (aR[1][1][i] + aR[1][2][i]);
        sZ[i]  = (aZ[0][0][i] + aZ[0][1][i]) + (aZ[0][2][i] + aZ[1][0][i])
               + (aZ[1][1][i] + aZ[1][2][i]);
        sN[i]  = (aN[0][0][i] + aN[0][1][i]) + (aN[0][2][i] + aN[1][0][i])
               + (aN[1][1][i] + aN[1][2][i]);
        sNx[i] = (aNx[0][0][i] + aNx[0][1][i]) + (aNx[0][2][i] + aNx[1][0][i])
               + (aNx[1][1][i] + aNx[1][2][i]);
    }

    #pragma unroll
    for (int rr = 0; rr < 2; rr++) {
        const int lrow = w * 16 + (lane >> 2) + rr * 8;
        const int row  = bt * 128 + lrow;
        const int i0 = rr * 2;

        float2 hpv = (t == 0)
            ? *(const float2*)(h0 + (size_t)row * Hh + mg)
            : *(const float2*)(out + ((size_t)row * Tt + (t - 1)) * Hh + mg);

        float rl = sigf(sR[i0]   + cR.x);
        float rh = sigf(sR[i0+1] + cR.y);
        float zl = sigf(sZ[i0]   + cZ.x);
        float zh = sigf(sZ[i0+1] + cZ.y);
        float nl = tanhf(sNx[i0]   + cNx.x + rl * (sN[i0]   + cNh.x));
        float nh = tanhf(sNx[i0+1] + cNx.y + rh * (sN[i0+1] + cNh.y));
        float hl = (1.f - zl) * nl + zl * hpv.x;
        float hh = (1.f - zh) * nh + zh * hpv.y;
        hl = fminf(fmaxf(hl, -CLIPV), CLIPV);
        hh = fminf(fmaxf(hh, -CLIPV), CLIPV);

        *(float2*)(out + ((size_t)row * Tt + t) * Hh + mg) = make_float2(hl, hh);
        if (t == Tt - 1)
            *(float2*)(out + (size_t)Bsz * Tt * Hh + (size_t)row * Hh + mg)
                = make_float2(hl, hh);

        unsigned short lh, ll, hhh, hhl;
        bf16hl(hl, lh, ll);
        bf16hl(hh, hhh, hhl);
        *(unsigned*)&g_himg[ph ^ 1][bt][0][lrow][mg * 2] = lh | (unsigned)hhh << 16;
        *(unsigned*)&g_himg[ph ^ 1][bt][1][lrow][mg * 2] = ll | (unsigned)hhl << 16;
    }
}

extern "C" void kernel_launch(void* const* d_in, const int* in_sizes, int n_in,
                              void* d_out, int out_size)
{
    (void)in_sizes; (void)n_in; (void)out_size;
    const float* x    = (const float*)d_in[0];
    const float* h0   = (const float*)d_in[1];
    const float* w_ih = (const float*)d_in[2];
    const float* w_hh = (const float*)d_in[3];
    const float* b_ih = (const float*)d_in[4];
    const float* b_hh = (const float*)d_in[5];
    float* out = (float*)d_out;

    cudaFuncSetAttribute(gru_step, cudaFuncAttributeMaxDynamicSharedMemorySize,
                         SMEM_BYTES);

    pack_w<<<(64 * 40 * 32 + 255) / 256, 256>>>(w_ih, w_hh);
    conv_h0<<<(2 * 128 * 64) / 256, 256>>>(h0);
    conv_x<<<Tt * 16, 256>>>(x);

    dim3 grid(64, 2);
    for (int t = 0; t < Tt; t++)
        gru_step<<<grid, NTHR, SMEM_BYTES>>>(t, h0, b_ih, b_hh, out);
}

// round 17
// speedup vs baseline: 3.1012x; 1.1257x over previous
#include <cuda_runtime.h>
#include <cuda_bf16.h>
#include <cstdint>
#include <math.h>

#define Bsz 256
#define Tt  500
#define Ii  128
#define Hh  512
#define CLIPV 5.0f

#define NTHR 256
// smem: B fragments [40 kstep][3 gate][32 lane] uint4 = 61440
//       A rings: 8 warps x 4 slots x (2 sub x 2 plane x 16 row x 80B) = 163840
#define WB_U4  3840
#define SM_A   61440
#define WRING  20480      // per-warp ring (4 slots x 5120)
#define SLOT   5120
#define SMEM_BYTES (SM_A + 8 * WRING)   // 225280

// pre-swizzled bf16 hi/lo plane images
__device__ __align__(16) unsigned char g_himg[2][2][2][128][1024];  // [phase][bt][plane][row][512k*2B]
__device__ __align__(16) unsigned char g_ximg[Tt][2][2][128][256];  // [t][bt][plane][row][128k*2B]
__device__ __align__(16) uint4 g_wb[64 * WB_U4];                    // [nt][kstep][gate][lane]

__device__ __forceinline__ uint32_t smem_u32(const void* p) {
    uint32_t a;
    asm("{ .reg .u64 t; cvta.to.shared.u64 t, %1; cvt.u32.u64 %0, t; }" : "=r"(a) : "l"(p));
    return a;
}
__device__ __forceinline__ void bf16hl(float v, unsigned short& hi, unsigned short& lo) {
    __nv_bfloat16 h = __float2bfloat16_rn(v);
    __nv_bfloat16 l = __float2bfloat16_rn(v - __bfloat162float(h));
    hi = __bfloat16_as_ushort(h);
    lo = __bfloat16_as_ushort(l);
}
__device__ __forceinline__ float sigf(float x) { return 1.f / (1.f + __expf(-x)); }
__device__ __forceinline__ void cp16(uint32_t dst, const void* src) {
    asm volatile("cp.async.cg.shared.global [%0], [%1], 16;"
                 :: "r"(dst), "l"(src) : "memory");
}

#define MMA_BF16(D, A0, A1, A2, A3, B0, B1)                               \
    asm volatile("mma.sync.aligned.m16n8k16.row.col.f32.bf16.bf16.f32 "   \
                 "{%0,%1,%2,%3},{%4,%5,%6,%7},{%8,%9},{%0,%1,%2,%3};"     \
                 : "+f"(D[0]), "+f"(D[1]), "+f"(D[2]), "+f"(D[3])         \
                 : "r"(A0), "r"(A1), "r"(A2), "r"(A3), "r"(B0), "r"(B1))

#define LDSM4(R0, R1, R2, R3, ADDR)                                       \
    asm volatile("ldmatrix.sync.aligned.m8n8.x4.shared.b16 {%0,%1,%2,%3}, [%4];" \
                 : "=r"(R0), "=r"(R1), "=r"(R2), "=r"(R3) : "r"(ADDR))

// ---------------- one-time pre-kernels (idempotent) ----------------
__global__ void conv_x(const float* __restrict__ x) {
    int idx = blockIdx.x * 256 + threadIdx.x;
    int oct = idx & 15, b = (idx >> 4) & 255, t = idx >> 12;
    if (t >= Tt) return;
    int k0 = oct * 8, bt = b >> 7, row = b & 127;
    const float* p = x + ((size_t)b * Tt + t) * Ii + k0;
    float4 v0 = __ldcg((const float4*)p), v1 = __ldcg((const float4*)(p + 4));
    float vs[8] = {v0.x, v0.y, v0.z, v0.w, v1.x, v1.y, v1.z, v1.w};
    unsigned short h[8], l[8];
    #pragma unroll
    for (int e = 0; e < 8; e++) bf16hl(vs[e], h[e], l[e]);
    uint4 hv = make_uint4(h[0]|(unsigned)h[1]<<16, h[2]|(unsigned)h[3]<<16,
                          h[4]|(unsigned)h[5]<<16, h[6]|(unsigned)h[7]<<16);
    uint4 lv = make_uint4(l[0]|(unsigned)l[1]<<16, l[2]|(unsigned)l[3]<<16,
                          l[4]|(unsigned)l[5]<<16, l[6]|(unsigned)l[7]<<16);
    *(uint4*)&g_ximg[t][bt][0][row][k0 * 2] = hv;
    *(uint4*)&g_ximg[t][bt][1][row][k0 * 2] = lv;
}

__global__ void conv_h0(const float* __restrict__ h0) {
    int idx = blockIdx.x * 256 + threadIdx.x;
    int oct = idx & 63, row = (idx >> 6) & 127, bt = idx >> 13;
    int k0 = oct * 8;
    const float* p = h0 + (size_t)(bt * 128 + row) * Hh + k0;
    float4 v0 = __ldcg((const float4*)p), v1 = __ldcg((const float4*)(p + 4));
    float vs[8] = {v0.x, v0.y, v0.z, v0.w, v1.x, v1.y, v1.z, v1.w};
    unsigned short h[8], l[8];
    #pragma unroll
    for (int e = 0; e < 8; e++) bf16hl(vs[e], h[e], l[e]);
    uint4 hv = make_uint4(h[0]|(unsigned)h[1]<<16, h[2]|(unsigned)h[3]<<16,
                          h[4]|(unsigned)h[5]<<16, h[6]|(unsigned)h[7]<<16);
    uint4 lv = make_uint4(l[0]|(unsigned)l[1]<<16, l[2]|(unsigned)l[3]<<16,
                          l[4]|(unsigned)l[5]<<16, l[6]|(unsigned)l[7]<<16);
    *(uint4*)&g_himg[0][bt][0][row][k0 * 2] = hv;
    *(uint4*)&g_himg[0][bt][1][row][k0 * 2] = lv;
}

__global__ void pack_w(const float* __restrict__ w_ih, const float* __restrict__ w_hh) {
    int idx = blockIdx.x * 256 + threadIdx.x;
    if (idx >= 64 * 40 * 32) return;
    int lane = idx & 31, kstep = (idx >> 5) % 40, nt = idx / (32 * 40);
    int kb = kstep * 16 + 2 * (lane & 3);
    #pragma unroll
    for (int g = 0; g < 3; g++) {
        int n = g * Hh + nt * 8 + (lane >> 2);
        float v[4];
        #pragma unroll
        for (int e = 0; e < 4; e++) {
            int k = kb + (e >> 1) * 8 + (e & 1);
            v[e] = (k < Hh) ? w_hh[(size_t)n * Hh + k] : w_ih[(size_t)n * Ii + (k - Hh)];
        }
        unsigned short h[4], l[4];
        #pragma unroll
        for (int e = 0; e < 4; e++) bf16hl(v[e], h[e], l[e]);
        g_wb[(size_t)((nt * 40 + kstep) * 3 + g) * 32 + lane] =
            make_uint4(h[0]|(unsigned)h[1]<<16, h[2]|(unsigned)h[3]<<16,
                       l[0]|(unsigned)l[1]<<16, l[2]|(unsigned)l[3]<<16);
    }
}

// ---------------- one GRU timestep ----------------
// grid (64 nt, 2 bt) x 256 threads. Warp w: batch rows 16w..16w+15, all 24 outs,
// K=640 (40 k16-steps, 10 chunks of 64k). Warp-private cp.async staging,
// no intra-step barriers, fully unrolled. bf16x3 split accumulators.
// cp.async invariant: EVERY iteration commits exactly one group (empty at tail),
// so wait_group 3 at iteration c guarantees chunks 0..c complete.
__global__ void __launch_bounds__(NTHR, 1) gru_step(
    int t,
    const float* __restrict__ h0,
    const float* __restrict__ b_ih,
    const float* __restrict__ b_hh,
    float* __restrict__ out)
{
    extern __shared__ char smx[];
    const uint32_t smb = smem_u32(smx);

    const int tid = threadIdx.x, lane = tid & 31, w = tid >> 5;
    const int nt = blockIdx.x, bt = blockIdx.y;
    const int ph = t & 1;

    // ---- hoisted epilogue inputs (stream-ordered, safe) ----
    const int mg = nt * 8 + 2 * (lane & 3);
    const float2 cR  = make_float2(b_ih[mg] + b_hh[mg], b_ih[mg+1] + b_hh[mg+1]);
    const float2 cZ  = make_float2(b_ih[Hh+mg] + b_hh[Hh+mg], b_ih[Hh+mg+1] + b_hh[Hh+mg+1]);
    const float2 cNx = make_float2(b_ih[2*Hh+mg], b_ih[2*Hh+mg+1]);
    const float2 cNh = make_float2(b_hh[2*Hh+mg], b_hh[2*Hh+mg+1]);
    float2 hpv[2];
    #pragma unroll
    for (int rr = 0; rr < 2; rr++) {
        const int row = bt * 128 + w * 16 + (lane >> 2) + rr * 8;
        hpv[rr] = (t == 0)
            ? *(const float2*)(h0 + (size_t)row * Hh + mg)
            : *(const float2*)(out + ((size_t)row * Tt + (t - 1)) * Hh + mg);
    }

    // B fragments -> smem (cooperative; the ONLY block barrier)
    {
        const uint4* src = g_wb + (size_t)nt * WB_U4;
        uint4* dst = (uint4*)smx;
        #pragma unroll
        for (int i = 0; i < 15; i++) dst[tid + i * 256] = __ldcg(src + tid + i * 256);
    }

    // accumulators: [parity][term][4]
    __align__(16) float aR[2][3][4], aZ[2][3][4], aN[2][3][4], aNx[2][3][4];
    #pragma unroll
    for (int p = 0; p < 2; p++)
        #pragma unroll
        for (int q = 0; q < 3; q++)
            #pragma unroll
            for (int i = 0; i < 4; i++)
                { aR[p][q][i]=0.f; aZ[p][q][i]=0.f; aN[p][q][i]=0.f; aNx[p][q][i]=0.f; }

    const uint32_t wring = smb + SM_A + w * WRING;

    // per-lane decode for the 8 cp.async of a chunk: i = lane + 32q over
    // (s:1)(p:1)(row:4)(col16:2)
    auto cp_chunk = [&](int c) {
        const int k0 = c * 64;
        const uint32_t slot = wring + (c & 3) * SLOT;
        #pragma unroll
        for (int q = 0; q < 8; q++) {
            const int i = lane + 32 * q;
            const int col4 = i & 3, row = (i >> 2) & 15, p = (i >> 6) & 1, s = i >> 7;
            const int grow = w * 16 + row;
            const unsigned char* src = (k0 < Hh)
                ? &g_himg[ph][bt][p][grow][(k0 + s * 32) * 2 + col4 * 16]
                : &g_ximg[t][bt][p][grow][(k0 - Hh + s * 32) * 2 + col4 * 16];
            cp16(slot + s * 2560 + p * 1280 + row * 80 + col4 * 16, src);
        }
        asm volatile("cp.async.commit_group;" ::: "memory");
    };

    auto compute = [&](int j, int jj, bool isH) {   // j global kstep, jj = j&3
        const int par = jj & 1;
        const int sub = (jj >> 1) & 1;
        const uint4* Bs = (const uint4*)smx;
        uint4 b0 = Bs[(j * 3 + 0) * 32 + lane];
        uint4 b1 = Bs[(j * 3 + 1) * 32 + lane];
        uint4 b2 = Bs[(j * 3 + 2) * 32 + lane];
        const uint32_t pb  = wring + ((j >> 2) & 3) * SLOT + sub * 2560;
        const uint32_t lad = (lane & 15) * 80 + (lane >> 4) * 16 + par * 32;
        uint32_t ah0, ah1, ah2, ah3, al0, al1, al2, al3;
        LDSM4(ah0, ah1, ah2, ah3, pb + lad);
        LDSM4(al0, al1, al2, al3, pb + 1280 + lad);
        float (*DN)[4] = isH ? aN[par] : aNx[par];
        MMA_BF16(aR[par][0], ah0, ah1, ah2, ah3, b0.x, b0.y);
        MMA_BF16(aZ[par][0], ah0, ah1, ah2, ah3, b1.x, b1.y);
        MMA_BF16(DN[0],      ah0, ah1, ah2, ah3, b2.x, b2.y);
        MMA_BF16(aR[par][1], ah0, ah1, ah2, ah3, b0.z, b0.w);
        MMA_BF16(aZ[par][1], ah0, ah1, ah2, ah3, b1.z, b1.w);
        MMA_BF16(DN[1],      ah0, ah1, ah2, ah3, b2.z, b2.w);
        MMA_BF16(aR[par][2], al0, al1, al2, al3, b0.x, b0.y);
        MMA_BF16(aZ[par][2], al0, al1, al2, al3, b1.x, b1.y);
        MMA_BF16(DN[2],      al0, al1, al2, al3, b2.x, b2.y);
    };

    // prologue: 3 chunks in flight
    cp_chunk(0);
    cp_chunk(1);
    cp_chunk(2);
    __syncthreads();    // B fragments visible (cp.async unaffected)

    #pragma unroll
    for (int c = 0; c < 10; c++) {
        if (c + 3 < 10) cp_chunk(c + 3);
        else asm volatile("cp.async.commit_group;" ::: "memory");  // empty group:
                                             // keeps commits == c+4 so wait covers chunk c
        asm volatile("cp.async.wait_group 3;" ::: "memory");       // chunk c complete
        const bool isH = (c < 8);
        #pragma unroll
        for (int jj = 0; jj < 4; jj++)
            compute(4 * c + jj, jj, isH);
    }

    // ---- gates epilogue ----
    float sR[4], sZ[4], sN[4], sNx[4];
    #pragma unroll
    for (int i = 0; i < 4; i++) {
        sR[i]  = (aR[0][0][i] + aR[0][1][i]) + (aR[0][2][i] + aR[1][0][i])
               + (aR[1][1][i] + aR[1][2][i]);
        sZ[i]  = (aZ[0][0][i] + aZ[0][1][i]) + (aZ[0][2][i] + aZ[1][0][i])
               + (aZ[1][1][i] + aZ[1][2][i]);
        sN[i]  = (aN[0][0][i] + aN[0][1][i]) + (aN[0][2][i] + aN[1][0][i])
               + (aN[1][1][i] + aN[1][2][i]);
        sNx[i] = (aNx[0][0][i] + aNx[0][1][i]) + (aNx[0][2][i] + aNx[1][0][i])
               + (aNx[1][1][i] + aNx[1][2][i]);
    }

    #pragma unroll
    for (int rr = 0; rr < 2; rr++) {
        const int lrow = w * 16 + (lane >> 2) + rr * 8;
        const int row  = bt * 128 + lrow;
        const int i0 = rr * 2;

        float rl = sigf(sR[i0]   + cR.x);
        float rh = sigf(sR[i0+1] + cR.y);
        float zl = sigf(sZ[i0]   + cZ.x);
        float zh = sigf(sZ[i0+1] + cZ.y);
        float nl = tanhf(sNx[i0]   + cNx.x + rl * (sN[i0]   + cNh.x));
        float nh = tanhf(sNx[i0+1] + cNx.y + rh * (sN[i0+1] + cNh.y));
        float hl = (1.f - zl) * nl + zl * hpv[rr].x;
        float hh = (1.f - zh) * nh + zh * hpv[rr].y;
        hl = fminf(fmaxf(hl, -CLIPV), CLIPV);
        hh = fminf(fmaxf(hh, -CLIPV), CLIPV);

        *(float2*)(out + ((size_t)row * Tt + t) * Hh + mg) = make_float2(hl, hh);
        if (t == Tt - 1)
            *(float2*)(out + (size_t)Bsz * Tt * Hh + (size_t)row * Hh + mg)
                = make_float2(hl, hh);

        unsigned short lh, ll, hhh, hhl;
        bf16hl(hl, lh, ll);
        bf16hl(hh, hhh, hhl);
        *(unsigned*)&g_himg[ph ^ 1][bt][0][lrow][mg * 2] = lh | (unsigned)hhh << 16;
        *(unsigned*)&g_himg[ph ^ 1][bt][1][lrow][mg * 2] = ll | (unsigned)hhl << 16;
    }
}

extern "C" void kernel_launch(void* const* d_in, const int* in_sizes, int n_in,
                              void* d_out, int out_size)
{
    (void)in_sizes; (void)n_in; (void)out_size;
    const float* x    = (const float*)d_in[0];
    const float* h0   = (const float*)d_in[1];
    const float* w_ih = (const float*)d_in[2];
    const float* w_hh = (const float*)d_in[3];
    const float* b_ih = (const float*)d_in[4];
    const float* b_hh = (const float*)d_in[5];
    float* out = (float*)d_out;

    cudaFuncSetAttribute(gru_step, cudaFuncAttributeMaxDynamicSharedMemorySize,
                         SMEM_BYTES);

    pack_w<<<(64 * 40 * 32 + 255) / 256, 256>>>(w_ih, w_hh);
    conv_h0<<<(2 * 128 * 64) / 256, 256>>>(h0);
    conv_x<<<Tt * 16, 256>>>(x);

    dim3 grid(64, 2);
    for (int t = 0; t < Tt; t++)
        gru_step<<<grid, NTHR, SMEM_BYTES>>>(t, h0, b_ih, b_hh, out);
}